// round 15
// baseline (speedup 1.0000x reference)
#include <cuda_runtime.h>
#include <cuda_fp16.h>
#include <cstdint>

#define B_  8
#define S_  4096
#define D_  256
#define DV_ 256
#define EPS_ 1e-6f

#define SPLITS 8
#define S_PER  (S_ / SPLITS)     // 512
#define KC     32                // k-chunk
#define NT     128               // threads per CTA (4 warps)

// ---------------- kv_kernel smem ------------------------------------------
// raw fp32 staging (single buffer) + fp16 tiles (double buffer)
#define RAWLD  272               // 64 fp32 = 256B + 16 pad
#define RAWA   0                 // 32 rows x 272 = 8704
#define RAWB   8704
#define LDA_KV 144               // 64 fp16 = 128B + 16 pad
#define LDB_KV 144
#define A_TILE_KV (KC * LDA_KV)  // 4608
#define OFFK_A 0
#define OFFK_B A_TILE_KV
#define BUF_KV (2 * A_TILE_KV)   // 9216
#define FP16BASE 17408
#define SMEM_KV (FP16BASE + 2 * BUF_KV)   // 35840

// ---------------- out_kernel smem: [row][k] fp16 tiles (round-14) ----------
#define LDSB   80
#define TILEA64  (64 * LDSB)     // 5120
#define TILEB128 (128 * LDSB)    // 10240
#define OFF_A 0
#define OFF_B TILEA64
#define BUF_OUT (TILEA64 + TILEB128)   // 15360
#define SMEM_OUT (2 * BUF_OUT)         // 30720

__device__ float g_part[SPLITS * B_ * DV_ * D_];   // 16 MB fp32 split-S partials
__device__ __half g_KVTh[B_ * DV_ * D_];           // KV^T fp16 [b][v][d]

// ---------------------------------------------------------------------------
__device__ __forceinline__ uint32_t smem_to_u32(const void* p) {
    uint32_t a;
    asm("{ .reg .u64 t; cvta.to.shared.u64 t, %1; cvt.u32.u64 %0, t; }"
        : "=r"(a) : "l"(p));
    return a;
}
__device__ __forceinline__ void ldmx4(uint32_t* r, uint32_t addr) {
    asm volatile("ldmatrix.sync.aligned.m8n8.x4.shared.b16 {%0,%1,%2,%3}, [%4];"
        : "=r"(r[0]), "=r"(r[1]), "=r"(r[2]), "=r"(r[3]) : "r"(addr));
}
__device__ __forceinline__ void ldmx4t(uint32_t* r, uint32_t addr) {
    asm volatile("ldmatrix.sync.aligned.m8n8.x4.trans.shared.b16 {%0,%1,%2,%3}, [%4];"
        : "=r"(r[0]), "=r"(r[1]), "=r"(r[2]), "=r"(r[3]) : "r"(addr));
}
__device__ __forceinline__ void mma16816h(float* c, const uint32_t* a, const uint32_t* b) {
    asm volatile(
        "mma.sync.aligned.m16n8k16.row.col.f32.f16.f16.f32 "
        "{%0,%1,%2,%3}, {%4,%5,%6,%7}, {%8,%9}, {%0,%1,%2,%3};"
        : "+f"(c[0]), "+f"(c[1]), "+f"(c[2]), "+f"(c[3])
        : "r"(a[0]), "r"(a[1]), "r"(a[2]), "r"(a[3]), "r"(b[0]), "r"(b[1]));
}
__device__ __forceinline__ void cp_async16(uint32_t dst, const void* src) {
    asm volatile("cp.async.cg.shared.global [%0], [%1], 16;"
        :: "r"(dst), "l"(src) : "memory");
}
#define CP_COMMIT() asm volatile("cp.async.commit_group;" ::: "memory")
#define CP_WAIT0()  asm volatile("cp.async.wait_group 0;" ::: "memory")

__device__ __forceinline__ uint32_t cvt2h(float x0, float x1) {
    uint32_t r;
    asm("cvt.rn.f16x2.f32 %0, %1, %2;" : "=r"(r) : "f"(x1), "f"(x0));
    return r;
}

// ---------------------------------------------------------------------------
// kv MMA chunk: fp16 tiles [k][col] (64-wide), ldmatrix.trans. Warp 32x32.
// ---------------------------------------------------------------------------
__device__ __forceinline__ void warp_chunk_mma_kv(
    uint32_t buf, int lane, int wm, int wn, float (*acc)[4])
{
    const uint32_t aT = buf + OFFK_A, bT = buf + OFFK_B;
#pragma unroll
    for (int ks = 0; ks < 2; ks++) {
        int krA = ks * 16 + (lane & 7) + ((lane >> 4) & 1) * 8;
        int mcA = wm + ((lane >> 3) & 1) * 8;
        uint32_t aoff = (uint32_t)(krA * LDA_KV + mcA * 2);
        uint32_t ah[2][4];
#pragma unroll
        for (int mi = 0; mi < 2; mi++)
            ldmx4t(ah[mi], aT + aoff + mi * 32);

        int krB = ks * 16 + (lane & 7) + ((lane >> 3) & 1) * 8;
        int ncB = wn + (lane >> 4) * 8;
        uint32_t boff = (uint32_t)(krB * LDB_KV + ncB * 2);
        uint32_t bh[4][2];
#pragma unroll
        for (int pi = 0; pi < 2; pi++) {
            uint32_t r4[4];
            ldmx4t(r4, bT + boff + pi * 32);
            bh[2*pi][0] = r4[0]; bh[2*pi][1] = r4[1];
            bh[2*pi+1][0] = r4[2]; bh[2*pi+1][1] = r4[3];
        }
#pragma unroll
        for (int mi = 0; mi < 2; mi++)
#pragma unroll
            for (int ni = 0; ni < 4; ni++)
                mma16816h(acc[mi * 4 + ni], ah[mi], bh[ni]);
    }
}

// out MMA chunk: fp16 tiles [row][k], warp tile 32x64 (8 n-frags).
__device__ __forceinline__ void warp_chunk_mma_out(
    uint32_t buf, int lane, int wm, int wn, float (*acc)[4])
{
    const uint32_t aT = buf + OFF_A, bT = buf + OFF_B;
#pragma unroll
    for (int ks = 0; ks < 2; ks++) {
        uint32_t aoff = (uint32_t)((wm + (lane & 15)) * LDSB
                                   + ((lane >> 4) * 8 + ks * 16) * 2);
        uint32_t ah[2][4];
#pragma unroll
        for (int mi = 0; mi < 2; mi++)
            ldmx4(ah[mi], aT + aoff + mi * 16 * LDSB);

        uint32_t boff = (uint32_t)((wn + (lane & 7) + ((lane >> 4) << 3)) * LDSB
                                   + (((lane >> 3) & 1) * 8 + ks * 16) * 2);
        uint32_t bh[8][2];
#pragma unroll
        for (int pi = 0; pi < 4; pi++) {
            uint32_t r4[4];
            ldmx4(r4, bT + boff + pi * 16 * LDSB);
            bh[2*pi][0] = r4[0]; bh[2*pi][1] = r4[1];
            bh[2*pi+1][0] = r4[2]; bh[2*pi+1][1] = r4[3];
        }
#pragma unroll
        for (int mi = 0; mi < 2; mi++)
#pragma unroll
            for (int ni = 0; ni < 8; ni++)
                mma16816h(acc[mi * 8 + ni], ah[mi], bh[ni]);
    }
}

// ---------------------------------------------------------------------------
// Kernel 1: partial KV^T[v,d] = sum_{s in split} V[s,v] * (relu(K[s,d])+eps)
// cp.async raw fp32 -> smem transform -> fp16 tiles. occ 5 target.
// Grid (16, SPLITS=8, B) = 1024 CTAs.
// ---------------------------------------------------------------------------
__global__ __launch_bounds__(NT, 5)
void kv_kernel(const float* __restrict__ K, const float* __restrict__ V) {
    extern __shared__ __align__(16) char smem[];
    const uint32_t sb = smem_to_u32(smem);

    const int t = threadIdx.x, lane = t & 31, wid = t >> 5;
    const int wm = (wid & 1) * 32, wn = (wid >> 1) * 32;
    const int b = blockIdx.z, p = blockIdx.y;
    const int v0 = (blockIdx.x & 3) * 64, d0 = (blockIdx.x >> 2) * 64;

    const float* __restrict__ Vb = V + (size_t)b * S_ * DV_;
    const float* __restrict__ Kb = K + (size_t)b * S_ * D_;

    float acc[8][4];
#pragma unroll
    for (int i = 0; i < 8; i++)
#pragma unroll
        for (int j = 0; j < 4; j++) acc[i][j] = 0.0f;

    // cp.async slots (j<4): idx = t + j*128; row = idx>>4 (0..31), seg = idx&15
    // prologue: raw(0)
    {
        const int s_c = p * S_PER;
#pragma unroll
        for (int j = 0; j < 4; j++) {
            int idx = t + j * NT;
            int row = idx >> 4, seg = idx & 15;
            uint32_t doff = (uint32_t)(row * RAWLD + seg * 16);
            cp_async16(sb + RAWA + doff, Vb + (size_t)(s_c + row) * DV_ + v0 + seg * 4);
            cp_async16(sb + RAWB + doff, Kb + (size_t)(s_c + row) * D_ + d0 + seg * 4);
        }
        CP_COMMIT();
    }

    const int NC = S_PER / KC;   // 16
    for (int c = 0; c < NC; c++) {
        CP_WAIT0();
        __syncthreads();                       // raw(c) visible to all
        char* fbuf = smem + FP16BASE + (size_t)(c & 1) * BUF_KV;
#pragma unroll
        for (int i = 0; i < 4; i++) {
            int idx = t + i * NT;
            int s = idx >> 4, c4 = idx & 15;
            float4 av = *(const float4*)(smem + RAWA + s * RAWLD + c4 * 16);
            *(uint2*)(fbuf + OFFK_A + s * LDA_KV + c4 * 8) =
                make_uint2(cvt2h(av.x, av.y), cvt2h(av.z, av.w));
            float4 bv = *(const float4*)(smem + RAWB + s * RAWLD + c4 * 16);
            float b0 = fmaxf(bv.x, 0.f) + EPS_;
            float b1 = fmaxf(bv.y, 0.f) + EPS_;
            float b2 = fmaxf(bv.z, 0.f) + EPS_;
            float b3 = fmaxf(bv.w, 0.f) + EPS_;
            *(uint2*)(fbuf + OFFK_B + s * LDB_KV + c4 * 8) =
                make_uint2(cvt2h(b0, b1), cvt2h(b2, b3));
        }
        __syncthreads();                       // fp16 ready AND raw consumed
        if (c + 1 < NC) {
            const int s_c = p * S_PER + (c + 1) * KC;
#pragma unroll
            for (int j = 0; j < 4; j++) {
                int idx = t + j * NT;
                int row = idx >> 4, seg = idx & 15;
                uint32_t doff = (uint32_t)(row * RAWLD + seg * 16);
                cp_async16(sb + RAWA + doff, Vb + (size_t)(s_c + row) * DV_ + v0 + seg * 4);
                cp_async16(sb + RAWB + doff, Kb + (size_t)(s_c + row) * D_ + d0 + seg * 4);
            }
            CP_COMMIT();
        }
        warp_chunk_mma_kv(sb + FP16BASE + (uint32_t)(c & 1) * BUF_KV, lane, wm, wn, acc);
    }

    // Epilogue: C[v,d] -> g_part (fp32)
    float* dst = g_part + (size_t)(p * B_ + b) * DV_ * D_;
    const int rr = lane >> 2, cc = (lane & 3) * 2;
#pragma unroll
    for (int mi = 0; mi < 2; mi++)
#pragma unroll
        for (int ni = 0; ni < 4; ni++) {
            int row = v0 + wm + mi * 16 + rr;
            int col = d0 + wn + ni * 8 + cc;
            float* cp = acc[mi * 4 + ni];
            *(float2*)(dst + (size_t)row * D_ + col)       = make_float2(cp[0], cp[1]);
            *(float2*)(dst + (size_t)(row + 8) * D_ + col) = make_float2(cp[2], cp[3]);
        }
}

// ---------------------------------------------------------------------------
// Kernel 2: sum partials (fp32), single rn to fp16 KVT.
// ---------------------------------------------------------------------------
__global__ __launch_bounds__(256)
void reduce_kernel() {
    const int i = blockIdx.x * 256 + threadIdx.x;  // float4 group, 131072 total
    const size_t stride4 = (size_t)B_ * DV_ * D_ / 4;
    float4 acc = make_float4(0.f, 0.f, 0.f, 0.f);
#pragma unroll
    for (int p = 0; p < SPLITS; p++) {
        float4 v = ((const float4*)g_part)[p * stride4 + i];
        acc.x += v.x; acc.y += v.y; acc.z += v.z; acc.w += v.w;
    }
    ((uint2*)g_KVTh)[i] = make_uint2(cvt2h(acc.x, acc.y), cvt2h(acc.z, acc.w));
}

// ---------------------------------------------------------------------------
// Kernel 3: out[q,v] = (relu(Q)+eps)[q,d] @ KVT[v,d]^T  (round-14 proven)
// Tile 64(q) x 128(v), warp 32x64, occ 4. Grid (2, 64, B) = 1024 CTAs.
// ---------------------------------------------------------------------------
__global__ __launch_bounds__(NT, 4)
void out_kernel(const float* __restrict__ Q, float* __restrict__ O) {
    extern __shared__ __align__(16) char smem[];
    const uint32_t sb = smem_to_u32(smem);

    const int t = threadIdx.x, lane = t & 31, wid = t >> 5;
    const int wm = (wid & 1) * 32, wn = (wid >> 1) * 64;
    const int b = blockIdx.z;
    const int q0 = blockIdx.y * 64, v0 = blockIdx.x * 128;

    const float* __restrict__ Qb = Q + (size_t)b * S_ * D_;
    const __half* __restrict__ Ch = g_KVTh + (size_t)b * DV_ * D_;

    float acc[16][4];
#pragma unroll
    for (int i = 0; i < 16; i++)
#pragma unroll
        for (int j = 0; j < 4; j++) acc[i][j] = 0.0f;

    {
#pragma unroll
        for (int i = 0; i < 4; i++) {
            int idx = t + i * NT;
            int rowB = idx >> 2, sg = idx & 3;
            cp_async16(sb + OFF_B + (uint32_t)(rowB * LDSB + sg * 16),
                       Ch + (size_t)(v0 + rowB) * D_ + sg * 8);
        }
        CP_COMMIT();
    }
    float4 rq[4];
#pragma unroll
    for (int i = 0; i < 4; i++) {
        int idx = t + i * NT;
        rq[i] = *(const float4*)(Qb + (size_t)(q0 + (idx >> 3)) * D_ + (idx & 7) * 4);
    }

    const int NC = D_ / KC;   // 8
    for (int c = 0; c < NC; c++) {
        char* base = smem + (size_t)(c & 1) * BUF_OUT;
#pragma unroll
        for (int i = 0; i < 4; i++) {
            int idx = t + i * NT;
            int row = idx >> 3, f4 = idx & 7;
            float a0 = fmaxf(rq[i].x, 0.f) + EPS_;
            float a1 = fmaxf(rq[i].y, 0.f) + EPS_;
            float a2 = fmaxf(rq[i].z, 0.f) + EPS_;
            float a3 = fmaxf(rq[i].w, 0.f) + EPS_;
            *(uint2*)(base + OFF_A + row * LDSB + f4 * 8) =
                make_uint2(cvt2h(a0, a1), cvt2h(a2, a3));
        }
        CP_WAIT0();
        __syncthreads();
        if (c + 1 < NC) {
            const int dc = (c + 1) * KC;
            uint32_t nb = sb + (uint32_t)((~c & 1) * BUF_OUT);
#pragma unroll
            for (int i = 0; i < 4; i++) {
                int idx = t + i * NT;
                int rowB = idx >> 2, sg = idx & 3;
                cp_async16(nb + OFF_B + (uint32_t)(rowB * LDSB + sg * 16),
                           Ch + (size_t)(v0 + rowB) * D_ + dc + sg * 8);
            }
            CP_COMMIT();
#pragma unroll
            for (int i = 0; i < 4; i++) {
                int idx = t + i * NT;
                rq[i] = *(const float4*)(Qb + (size_t)(q0 + (idx >> 3)) * D_ + dc + (idx & 7) * 4);
            }
        }
        warp_chunk_mma_out(sb + (uint32_t)(c & 1) * BUF_OUT, lane, wm, wn, acc);
    }

    // Epilogue: C[q,v] -> O
    float* dst = O + (size_t)b * S_ * DV_;
    const int rr = lane >> 2, cc = (lane & 3) * 2;
#pragma unroll
    for (int mi = 0; mi < 2; mi++)
#pragma unroll
        for (int ni = 0; ni < 8; ni++) {
            int row = q0 + wm + mi * 16 + rr;
            int col = v0 + wn + ni * 8 + cc;
            float* cp = acc[mi * 8 + ni];
            *(float2*)(dst + (size_t)row * DV_ + col)       = make_float2(cp[0], cp[1]);
            *(float2*)(dst + (size_t)(row + 8) * DV_ + col) = make_float2(cp[2], cp[3]);
        }
}

extern "C" void kernel_launch(void* const* d_in, const int* in_sizes, int n_in,
                              void* d_out, int out_size) {
    const float* Q = (const float*)d_in[0];
    const float* K = (const float*)d_in[1];
    const float* V = (const float*)d_in[2];
    float* O = (float*)d_out;

    cudaFuncSetAttribute(kv_kernel,  cudaFuncAttributeMaxDynamicSharedMemorySize, SMEM_KV);
    cudaFuncSetAttribute(out_kernel, cudaFuncAttributeMaxDynamicSharedMemorySize, SMEM_OUT);

    kv_kernel<<<dim3(16, SPLITS, B_), NT, SMEM_KV>>>(K, V);
    reduce_kernel<<<512, 256>>>();
    out_kernel<<<dim3(2, 64, B_), NT, SMEM_OUT>>>(Q, O);
}

// round 16
// speedup vs baseline: 1.1624x; 1.1624x over previous
#include <cuda_runtime.h>
#include <cuda_fp16.h>
#include <cstdint>

#define B_  8
#define S_  4096
#define D_  256
#define DV_ 256
#define EPS_ 1e-6f

#define SPLITS 8
#define S_PER  (S_ / SPLITS)     // 512
#define KC     32                // k-chunk (fp16 elems)
#define NT     128               // threads per CTA (4 warps)

// ---------------- kv_kernel smem: [k][col] fp16 tiles, 64-wide -------------
#define LDA_KV 144               // 64 fp16 = 128B + 16 pad
#define LDB_KV 144
#define A_TILE_KV (KC * LDA_KV)  // 4608
#define OFFK_A 0
#define OFFK_B A_TILE_KV
#define BUF_KV (2 * A_TILE_KV)   // 9216
#define SMEM_KV (2 * BUF_KV)     // 18432

// ---------------- out_kernel smem: [row][k] fp16 tiles ----------------------
#define LDSB   80
#define TILEA64  (64 * LDSB)     // 5120
#define TILEB128 (128 * LDSB)    // 10240
#define OFF_A 0
#define OFF_B TILEA64
#define BUF_OUT (TILEA64 + TILEB128)   // 15360
#define SMEM_OUT (2 * BUF_OUT)         // 30720

__device__ float g_KV[B_ * DV_ * D_];              // 2 MB fp32 accumulator [b][v][d]
__device__ __half g_KVTh[B_ * DV_ * D_];           // KV^T fp16 [b][v][d]

// ---------------------------------------------------------------------------
__device__ __forceinline__ uint32_t smem_to_u32(const void* p) {
    uint32_t a;
    asm("{ .reg .u64 t; cvta.to.shared.u64 t, %1; cvt.u32.u64 %0, t; }"
        : "=r"(a) : "l"(p));
    return a;
}
__device__ __forceinline__ void ldmx4(uint32_t* r, uint32_t addr) {
    asm volatile("ldmatrix.sync.aligned.m8n8.x4.shared.b16 {%0,%1,%2,%3}, [%4];"
        : "=r"(r[0]), "=r"(r[1]), "=r"(r[2]), "=r"(r[3]) : "r"(addr));
}
__device__ __forceinline__ void ldmx4t(uint32_t* r, uint32_t addr) {
    asm volatile("ldmatrix.sync.aligned.m8n8.x4.trans.shared.b16 {%0,%1,%2,%3}, [%4];"
        : "=r"(r[0]), "=r"(r[1]), "=r"(r[2]), "=r"(r[3]) : "r"(addr));
}
__device__ __forceinline__ void mma16816h(float* c, const uint32_t* a, const uint32_t* b) {
    asm volatile(
        "mma.sync.aligned.m16n8k16.row.col.f32.f16.f16.f32 "
        "{%0,%1,%2,%3}, {%4,%5,%6,%7}, {%8,%9}, {%0,%1,%2,%3};"
        : "+f"(c[0]), "+f"(c[1]), "+f"(c[2]), "+f"(c[3])
        : "r"(a[0]), "r"(a[1]), "r"(a[2]), "r"(a[3]), "r"(b[0]), "r"(b[1]));
}
__device__ __forceinline__ void cp_async16(uint32_t dst, const void* src) {
    asm volatile("cp.async.cg.shared.global [%0], [%1], 16;"
        :: "r"(dst), "l"(src) : "memory");
}
#define CP_COMMIT() asm volatile("cp.async.commit_group;" ::: "memory")
#define CP_WAIT0()  asm volatile("cp.async.wait_group 0;" ::: "memory")

__device__ __forceinline__ uint32_t cvt2h(float x0, float x1) {
    uint32_t r;
    asm("cvt.rn.f16x2.f32 %0, %1, %2;" : "=r"(r) : "f"(x1), "f"(x0));
    return r;
}

// ---------------------------------------------------------------------------
// kv MMA chunk: fp16 tiles [k][col] (64-wide), ldmatrix.trans. Warp 32x32.
// ---------------------------------------------------------------------------
__device__ __forceinline__ void warp_chunk_mma_kv(
    uint32_t buf, int lane, int wm, int wn, float (*acc)[4])
{
    const uint32_t aT = buf + OFFK_A, bT = buf + OFFK_B;
#pragma unroll
    for (int ks = 0; ks < 2; ks++) {
        int krA = ks * 16 + (lane & 7) + ((lane >> 4) & 1) * 8;
        int mcA = wm + ((lane >> 3) & 1) * 8;
        uint32_t aoff = (uint32_t)(krA * LDA_KV + mcA * 2);
        uint32_t ah[2][4];
#pragma unroll
        for (int mi = 0; mi < 2; mi++)
            ldmx4t(ah[mi], aT + aoff + mi * 32);

        int krB = ks * 16 + (lane & 7) + ((lane >> 3) & 1) * 8;
        int ncB = wn + (lane >> 4) * 8;
        uint32_t boff = (uint32_t)(krB * LDB_KV + ncB * 2);
        uint32_t bh[4][2];
#pragma unroll
        for (int pi = 0; pi < 2; pi++) {
            uint32_t r4[4];
            ldmx4t(r4, bT + boff + pi * 32);
            bh[2*pi][0] = r4[0]; bh[2*pi][1] = r4[1];
            bh[2*pi+1][0] = r4[2]; bh[2*pi+1][1] = r4[3];
        }
#pragma unroll
        for (int mi = 0; mi < 2; mi++)
#pragma unroll
            for (int ni = 0; ni < 4; ni++)
                mma16816h(acc[mi * 4 + ni], ah[mi], bh[ni]);
    }
}

// out MMA chunk: fp16 tiles [row][k], warp tile 32x64 (8 n-frags).
__device__ __forceinline__ void warp_chunk_mma_out(
    uint32_t buf, int lane, int wm, int wn, float (*acc)[4])
{
    const uint32_t aT = buf + OFF_A, bT = buf + OFF_B;
#pragma unroll
    for (int ks = 0; ks < 2; ks++) {
        uint32_t aoff = (uint32_t)((wm + (lane & 15)) * LDSB
                                   + ((lane >> 4) * 8 + ks * 16) * 2);
        uint32_t ah[2][4];
#pragma unroll
        for (int mi = 0; mi < 2; mi++)
            ldmx4(ah[mi], aT + aoff + mi * 16 * LDSB);

        uint32_t boff = (uint32_t)((wn + (lane & 7) + ((lane >> 4) << 3)) * LDSB
                                   + (((lane >> 3) & 1) * 8 + ks * 16) * 2);
        uint32_t bh[8][2];
#pragma unroll
        for (int pi = 0; pi < 4; pi++) {
            uint32_t r4[4];
            ldmx4(r4, bT + boff + pi * 16 * LDSB);
            bh[2*pi][0] = r4[0]; bh[2*pi][1] = r4[1];
            bh[2*pi+1][0] = r4[2]; bh[2*pi+1][1] = r4[3];
        }
#pragma unroll
        for (int mi = 0; mi < 2; mi++)
#pragma unroll
            for (int ni = 0; ni < 8; ni++)
                mma16816h(acc[mi * 8 + ni], ah[mi], bh[ni]);
    }
}

// ---------------------------------------------------------------------------
// Kernel 0: zero the fp32 accumulator (graph-replay safe: runs every launch)
// ---------------------------------------------------------------------------
__global__ __launch_bounds__(256)
void zero_kernel() {
    ((float4*)g_KV)[blockIdx.x * 256 + threadIdx.x] =
        make_float4(0.f, 0.f, 0.f, 0.f);
}

// ---------------------------------------------------------------------------
// Kernel 1: KV^T[v,d] += sum_{s in split} V[s,v] * (relu(K[s,d])+eps)
// Round-14 body; epilogue uses atomicAdd (REDG) into g_KV.
// Grid (16, SPLITS=8, B) = 1024 CTAs, occ 4.
// ---------------------------------------------------------------------------
__global__ __launch_bounds__(NT, 4)
void kv_kernel(const float* __restrict__ K, const float* __restrict__ V) {
    extern __shared__ __align__(16) char smem[];
    const uint32_t sb = smem_to_u32(smem);

    const int t = threadIdx.x, lane = t & 31, wid = t >> 5;
    const int wm = (wid & 1) * 32, wn = (wid >> 1) * 32;
    const int b = blockIdx.z, p = blockIdx.y;
    const int v0 = (blockIdx.x & 3) * 64, d0 = (blockIdx.x >> 2) * 64;

    const float* __restrict__ Vb = V + (size_t)b * S_ * DV_;
    const float* __restrict__ Kb = K + (size_t)b * S_ * D_;

    float acc[8][4];
#pragma unroll
    for (int i = 0; i < 8; i++)
#pragma unroll
        for (int j = 0; j < 4; j++) acc[i][j] = 0.0f;

    // slots: idx = t + i*128 (i<4): s = idx>>4 (0..31), c4 = (idx&15)*4
    float4 ra[4], rb[4];
    {
        const int s_c = p * S_PER;
#pragma unroll
        for (int i = 0; i < 4; i++) {
            int idx = t + i * NT;
            int s = idx >> 4, c4 = (idx & 15) * 4;
            ra[i] = *(const float4*)(Vb + (size_t)(s_c + s) * DV_ + v0 + c4);
            rb[i] = *(const float4*)(Kb + (size_t)(s_c + s) * D_ + d0 + c4);
        }
    }

    const int NC = S_PER / KC;   // 16
    for (int c = 0; c < NC; c++) {
        char* base = smem + (size_t)(c & 1) * BUF_KV;
#pragma unroll
        for (int i = 0; i < 4; i++) {
            int idx = t + i * NT;
            int s = idx >> 4, c8 = (idx & 15) * 8;
            *(uint2*)(base + OFFK_A + s * LDA_KV + c8) =
                make_uint2(cvt2h(ra[i].x, ra[i].y), cvt2h(ra[i].z, ra[i].w));
            float b0 = fmaxf(rb[i].x, 0.f) + EPS_;
            float b1 = fmaxf(rb[i].y, 0.f) + EPS_;
            float b2 = fmaxf(rb[i].z, 0.f) + EPS_;
            float b3 = fmaxf(rb[i].w, 0.f) + EPS_;
            *(uint2*)(base + OFFK_B + s * LDB_KV + c8) =
                make_uint2(cvt2h(b0, b1), cvt2h(b2, b3));
        }
        __syncthreads();
        if (c + 1 < NC) {
            const int s_c = p * S_PER + (c + 1) * KC;
#pragma unroll
            for (int i = 0; i < 4; i++) {
                int idx = t + i * NT;
                int s = idx >> 4, c4 = (idx & 15) * 4;
                ra[i] = *(const float4*)(Vb + (size_t)(s_c + s) * DV_ + v0 + c4);
                rb[i] = *(const float4*)(Kb + (size_t)(s_c + s) * D_ + d0 + c4);
            }
        }
        warp_chunk_mma_kv(sb + (uint32_t)(c & 1) * BUF_KV, lane, wm, wn, acc);
    }

    // Epilogue: atomic-accumulate C[v,d] into g_KV (REDG, no return)
    float* dst = g_KV + (size_t)b * DV_ * D_;
    const int rr = lane >> 2, cc = (lane & 3) * 2;
#pragma unroll
    for (int mi = 0; mi < 2; mi++)
#pragma unroll
        for (int ni = 0; ni < 4; ni++) {
            int row = v0 + wm + mi * 16 + rr;
            int col = d0 + wn + ni * 8 + cc;
            float* cp = acc[mi * 4 + ni];
            atomicAdd(dst + (size_t)row * D_ + col,       cp[0]);
            atomicAdd(dst + (size_t)row * D_ + col + 1,   cp[1]);
            atomicAdd(dst + (size_t)(row + 8) * D_ + col,     cp[2]);
            atomicAdd(dst + (size_t)(row + 8) * D_ + col + 1, cp[3]);
        }
}

// ---------------------------------------------------------------------------
// Kernel 2: convert fp32 accumulator -> fp16 KVT.
// ---------------------------------------------------------------------------
__global__ __launch_bounds__(256)
void convert_kernel() {
    const int i = blockIdx.x * 256 + threadIdx.x;   // float4 group, 131072 total
    float4 v = ((const float4*)g_KV)[i];
    ((uint2*)g_KVTh)[i] = make_uint2(cvt2h(v.x, v.y), cvt2h(v.z, v.w));
}

// ---------------------------------------------------------------------------
// Kernel 3: out[q,v] = (relu(Q)+eps)[q,d] @ KVT[v,d]^T  (round-14 proven)
// Tile 64(q) x 128(v), warp 32x64, occ 4. Grid (2, 64, B) = 1024 CTAs.
// ---------------------------------------------------------------------------
__global__ __launch_bounds__(NT, 4)
void out_kernel(const float* __restrict__ Q, float* __restrict__ O) {
    extern __shared__ __align__(16) char smem[];
    const uint32_t sb = smem_to_u32(smem);

    const int t = threadIdx.x, lane = t & 31, wid = t >> 5;
    const int wm = (wid & 1) * 32, wn = (wid >> 1) * 64;
    const int b = blockIdx.z;
    const int q0 = blockIdx.y * 64, v0 = blockIdx.x * 128;

    const float* __restrict__ Qb = Q + (size_t)b * S_ * D_;
    const __half* __restrict__ Ch = g_KVTh + (size_t)b * DV_ * D_;

    float acc[16][4];
#pragma unroll
    for (int i = 0; i < 16; i++)
#pragma unroll
        for (int j = 0; j < 4; j++) acc[i][j] = 0.0f;

    {
#pragma unroll
        for (int i = 0; i < 4; i++) {
            int idx = t + i * NT;
            int rowB = idx >> 2, sg = idx & 3;
            cp_async16(sb + OFF_B + (uint32_t)(rowB * LDSB + sg * 16),
                       Ch + (size_t)(v0 + rowB) * D_ + sg * 8);
        }
        CP_COMMIT();
    }
    float4 rq[4];
#pragma unroll
    for (int i = 0; i < 4; i++) {
        int idx = t + i * NT;
        rq[i] = *(const float4*)(Qb + (size_t)(q0 + (idx >> 3)) * D_ + (idx & 7) * 4);
    }

    const int NC = D_ / KC;   // 8
    for (int c = 0; c < NC; c++) {
        char* base = smem + (size_t)(c & 1) * BUF_OUT;
#pragma unroll
        for (int i = 0; i < 4; i++) {
            int idx = t + i * NT;
            int row = idx >> 3, f4 = idx & 7;
            float a0 = fmaxf(rq[i].x, 0.f) + EPS_;
            float a1 = fmaxf(rq[i].y, 0.f) + EPS_;
            float a2 = fmaxf(rq[i].z, 0.f) + EPS_;
            float a3 = fmaxf(rq[i].w, 0.f) + EPS_;
            *(uint2*)(base + OFF_A + row * LDSB + f4 * 8) =
                make_uint2(cvt2h(a0, a1), cvt2h(a2, a3));
        }
        CP_WAIT0();
        __syncthreads();
        if (c + 1 < NC) {
            const int dc = (c + 1) * KC;
            uint32_t nb = sb + (uint32_t)((~c & 1) * BUF_OUT);
#pragma unroll
            for (int i = 0; i < 4; i++) {
                int idx = t + i * NT;
                int rowB = idx >> 2, sg = idx & 3;
                cp_async16(nb + OFF_B + (uint32_t)(rowB * LDSB + sg * 16),
                           Ch + (size_t)(v0 + rowB) * D_ + dc + sg * 8);
            }
            CP_COMMIT();
#pragma unroll
            for (int i = 0; i < 4; i++) {
                int idx = t + i * NT;
                rq[i] = *(const float4*)(Qb + (size_t)(q0 + (idx >> 3)) * D_ + dc + (idx & 7) * 4);
            }
        }
        warp_chunk_mma_out(sb + (uint32_t)(c & 1) * BUF_OUT, lane, wm, wn, acc);
    }

    // Epilogue: C[q,v] -> O
    float* dst = O + (size_t)b * S_ * DV_;
    const int rr = lane >> 2, cc = (lane & 3) * 2;
#pragma unroll
    for (int mi = 0; mi < 2; mi++)
#pragma unroll
        for (int ni = 0; ni < 8; ni++) {
            int row = q0 + wm + mi * 16 + rr;
            int col = v0 + wn + ni * 8 + cc;
            float* cp = acc[mi * 8 + ni];
            *(float2*)(dst + (size_t)row * DV_ + col)       = make_float2(cp[0], cp[1]);
            *(float2*)(dst + (size_t)(row + 8) * DV_ + col) = make_float2(cp[2], cp[3]);
        }
}

extern "C" void kernel_launch(void* const* d_in, const int* in_sizes, int n_in,
                              void* d_out, int out_size) {
    const float* Q = (const float*)d_in[0];
    const float* K = (const float*)d_in[1];
    const float* V = (const float*)d_in[2];
    float* O = (float*)d_out;

    cudaFuncSetAttribute(kv_kernel,  cudaFuncAttributeMaxDynamicSharedMemorySize, SMEM_KV);
    cudaFuncSetAttribute(out_kernel, cudaFuncAttributeMaxDynamicSharedMemorySize, SMEM_OUT);

    zero_kernel<<<512, 256>>>();
    kv_kernel<<<dim3(16, SPLITS, B_), NT, SMEM_KV>>>(K, V);
    convert_kernel<<<512, 256>>>();
    out_kernel<<<dim3(2, 64, B_), NT, SMEM_OUT>>>(Q, O);
}